// round 2
// baseline (speedup 1.0000x reference)
#include <cuda_runtime.h>
#include <math.h>

// ---------------- problem constants ----------------
#define BATCH 8
#define LSEQ  2048
#define EIN   64
#define MARK  4
#define CIN   68          // EIN + MARK
#define DM    256
#define DIN   512
#define DST   16
#define DTR   16
#define PL    96
#define COUT  64
#define MROWS (BATCH*LSEQ)   // 16384
#define CS    128            // scan chunk size
#define NCH   (LSEQ/CS)      // 16
#define NPRE  (NCH-1)        // 15 prefix chunks
#define LOUT0 (LSEQ-PL)      // 1952

// ---------------- scratch (static device memory; no allocs) ----------------
__device__ float g_cat [MROWS*CIN];
__device__ float g_x   [MROWS*DM];
__device__ float g_xp  [MROWS*DIN];
__device__ float g_z96 [BATCH*PL*DIN];
__device__ float g_xc  [MROWS*DIN];
__device__ float g_db  [MROWS*48];
__device__ float g_dt  [MROWS*DIN];
__device__ float g_P   [BATCH*NPRE*DIN*DST];
__device__ float g_Q   [BATCH*NPRE*DIN*DST];
__device__ float g_hin [BATCH*DIN*DST];
__device__ float g_y96 [BATCH*PL*DIN];
__device__ float g_wc  [COUT*DIN];

// ---------------- helpers ----------------
__device__ __forceinline__ float ex2_approx(float x) {
    float r;
    asm("ex2.approx.ftz.f32 %0, %1;" : "=f"(r) : "f"(x));
    return r;
}
__device__ __forceinline__ float fast_sigmoid(float x) {
    return 1.0f / (1.0f + __expf(-x));
}

// ---------------- K0: concat(x_enc, x_mark) ----------------
__global__ void concat_kernel(const float* __restrict__ xe,
                              const float* __restrict__ xm,
                              float* __restrict__ cat) {
    int idx = blockIdx.x * blockDim.x + threadIdx.x;
    if (idx >= MROWS * CIN) return;
    int c  = idx % CIN;
    int bl = idx / CIN;
    float v = (c < EIN) ? xe[(long)bl * EIN + c] : xm[(long)bl * MARK + (c - EIN)];
    cat[idx] = v;
}

// ---------------- generic fp32 SGEMM: C[M,N] = A[M,K(lda)] @ W[N,K]^T (+bias)(+act)
// BM=BN=64, BK=16, 128 threads, 4x8 per thread.
__global__ __launch_bounds__(128)
void sgemm_kernel(const float* __restrict__ A, const float* __restrict__ W,
                  const float* __restrict__ bias, float* __restrict__ C,
                  int M, int N, int K, int lda, int act, int remap) {
    __shared__ float As[16][65];
    __shared__ float Bs[16][65];
    int bm = blockIdx.y * 64;
    int bn = blockIdx.x * 64;
    int tid = threadIdx.x;
    int tx = tid % 8;   // col group (x8)
    int ty = tid / 8;   // row group (x4)
    float acc[4][8];
    #pragma unroll
    for (int i = 0; i < 4; i++)
        #pragma unroll
        for (int j = 0; j < 8; j++) acc[i][j] = 0.f;

    int kt = (K + 15) / 16;
    for (int t = 0; t < kt; ++t) {
        int k0 = t * 16;
        #pragma unroll
        for (int i = tid; i < 64 * 16; i += 128) {
            int m = i / 16, kk = i % 16;
            int gm = bm + m, gk = k0 + kk;
            float v = 0.f;
            if (gm < M && gk < K) {
                int row = gm;
                if (remap) row = (gm / PL) * LSEQ + LOUT0 + (gm % PL);
                v = A[(long)row * lda + gk];
            }
            As[kk][m] = v;
        }
        #pragma unroll
        for (int i = tid; i < 64 * 16; i += 128) {
            int n = i / 16, kk = i % 16;
            int gn = bn + n, gk = k0 + kk;
            float v = 0.f;
            if (gn < N && gk < K) v = W[(long)gn * K + gk];
            Bs[kk][n] = v;
        }
        __syncthreads();
        #pragma unroll
        for (int kk = 0; kk < 16; ++kk) {
            float a[4], bw[8];
            #pragma unroll
            for (int i = 0; i < 4; i++) a[i] = As[kk][ty * 4 + i];
            #pragma unroll
            for (int j = 0; j < 8; j++) bw[j] = Bs[kk][tx * 8 + j];
            #pragma unroll
            for (int i = 0; i < 4; i++)
                #pragma unroll
                for (int j = 0; j < 8; j++)
                    acc[i][j] = fmaf(a[i], bw[j], acc[i][j]);
        }
        __syncthreads();
    }
    #pragma unroll
    for (int i = 0; i < 4; i++) {
        int gm = bm + ty * 4 + i;
        if (gm >= M) continue;
        #pragma unroll
        for (int j = 0; j < 8; j++) {
            int gn = bn + tx * 8 + j;
            if (gn >= N) continue;
            float v = acc[i][j];
            if (bias) v += bias[gn];
            if (act == 1) {              // softplus
                v = (v > 20.f) ? v : log1pf(__expf(v));
            }
            C[(long)gm * N + gn] = v;
        }
    }
}

// ---------------- K3: causal depthwise conv(4) + bias + silu ----------------
__global__ void conv_silu_kernel(const float* __restrict__ xp,
                                 const float* __restrict__ cw,
                                 const float* __restrict__ cb,
                                 float* __restrict__ xc) {
    long idx = (long)blockIdx.x * blockDim.x + threadIdx.x;
    if (idx >= (long)MROWS * DIN) return;
    int d = (int)(idx & (DIN - 1));
    int l = (int)((idx >> 9) & (LSEQ - 1));
    float4 w = *(const float4*)(cw + d * 4);
    float acc = cb[d];
    if (l >= 3) acc = fmaf(xp[idx - 3 * DIN], w.x, acc);
    if (l >= 2) acc = fmaf(xp[idx - 2 * DIN], w.y, acc);
    if (l >= 1) acc = fmaf(xp[idx - 1 * DIN], w.z, acc);
    acc = fmaf(xp[idx], w.w, acc);
    xc[idx] = acc * fast_sigmoid(acc);
}

// ---------------- scan pass 1: prefix chunks -> (P, Q) ----------------
// block: 128 threads = 32 d x 4 nq (4 states each). grid: (16 dblk, B, NPRE)
__global__ __launch_bounds__(128)
void scan_pass1(const float* __restrict__ dt, const float* __restrict__ xc,
                const float* __restrict__ db, const float* __restrict__ A_log,
                float* __restrict__ P, float* __restrict__ Q) {
    int tid = threadIdx.x;
    int nq = tid & 3;
    int dl = tid >> 2;
    int d  = blockIdx.x * 32 + dl;
    int b  = blockIdx.y;
    int c  = blockIdx.z;
    int l0 = c * CS;
    const float LOG2E = 1.4426950408889634f;
    float c2[4];
    #pragma unroll
    for (int i = 0; i < 4; i++)
        c2[i] = -__expf(A_log[d * DST + nq * 4 + i]) * LOG2E;
    float h0 = 0.f, h1 = 0.f, h2 = 0.f, h3 = 0.f, S = 0.f;
    const float* dtp = dt + ((long)b * LSEQ + l0) * DIN + d;
    const float* xcp = xc + ((long)b * LSEQ + l0) * DIN + d;
    const float* dbp = db + ((long)b * LSEQ + l0) * 48 + 16 + nq * 4;
    #pragma unroll 4
    for (int l = 0; l < CS; ++l) {
        float dtv = dtp[(long)l * DIN];
        float xcv = xcp[(long)l * DIN];
        float4 Bm = *(const float4*)(dbp + (long)l * 48);
        S += dtv;
        float u = dtv * xcv;
        h0 = fmaf(ex2_approx(dtv * c2[0]), h0, u * Bm.x);
        h1 = fmaf(ex2_approx(dtv * c2[1]), h1, u * Bm.y);
        h2 = fmaf(ex2_approx(dtv * c2[2]), h2, u * Bm.z);
        h3 = fmaf(ex2_approx(dtv * c2[3]), h3, u * Bm.w);
    }
    long o = ((long)(b * NPRE + c) * DIN + d) * DST + nq * 4;
    *(float4*)(P + o) = make_float4(ex2_approx(S * c2[0]), ex2_approx(S * c2[1]),
                                    ex2_approx(S * c2[2]), ex2_approx(S * c2[3]));
    *(float4*)(Q + o) = make_float4(h0, h1, h2, h3);
}

// ---------------- scan pass 2: compose chunks -> h at start of last chunk ----
__global__ void scan_pass2(const float* __restrict__ P, const float* __restrict__ Q,
                           float* __restrict__ Hin) {
    int idx = blockIdx.x * blockDim.x + threadIdx.x;   // (b,d,nq)
    if (idx >= BATCH * DIN * 4) return;
    int nq = idx & 3;
    int d  = (idx >> 2) & (DIN - 1);
    int b  = idx >> 11;
    float4 h = make_float4(0.f, 0.f, 0.f, 0.f);
    for (int c = 0; c < NPRE; ++c) {
        long o = ((long)(b * NPRE + c) * DIN + d) * DST + nq * 4;
        float4 p = *(const float4*)(P + o);
        float4 q = *(const float4*)(Q + o);
        h.x = fmaf(p.x, h.x, q.x);
        h.y = fmaf(p.y, h.y, q.y);
        h.z = fmaf(p.z, h.z, q.z);
        h.w = fmaf(p.w, h.w, q.w);
    }
    *(float4*)(Hin + (long)idx * 4) = h;
}

// ---------------- scan pass 3: replay last chunk, emit gated y for last 96 ----
__global__ __launch_bounds__(128)
void scan_pass3(const float* __restrict__ dt, const float* __restrict__ xc,
                const float* __restrict__ db, const float* __restrict__ A_log,
                const float* __restrict__ Hin, const float* __restrict__ z96,
                const float* __restrict__ Dv, float* __restrict__ y96) {
    int tid = threadIdx.x;
    int nq = tid & 3;
    int dl = tid >> 2;
    int d  = blockIdx.x * 32 + dl;
    int b  = blockIdx.y;
    int l0 = (NCH - 1) * CS;   // 1920
    const float LOG2E = 1.4426950408889634f;
    float c2[4];
    #pragma unroll
    for (int i = 0; i < 4; i++)
        c2[i] = -__expf(A_log[d * DST + nq * 4 + i]) * LOG2E;
    float4 h = *(const float4*)(Hin + (((long)b * DIN + d) * DST + nq * 4));
    float Dd = Dv[d];
    const float* dtp = dt + ((long)b * LSEQ + l0) * DIN + d;
    const float* xcp = xc + ((long)b * LSEQ + l0) * DIN + d;
    const float* dbp = db + ((long)b * LSEQ + l0) * 48 + 16 + nq * 4;
    #pragma unroll 2
    for (int l = 0; l < CS; ++l) {
        float dtv = dtp[(long)l * DIN];
        float xcv = xcp[(long)l * DIN];
        float4 Bm = *(const float4*)(dbp + (long)l * 48);
        float4 Cm = *(const float4*)(dbp + (long)l * 48 + 16);
        float u = dtv * xcv;
        h.x = fmaf(ex2_approx(dtv * c2[0]), h.x, u * Bm.x);
        h.y = fmaf(ex2_approx(dtv * c2[1]), h.y, u * Bm.y);
        h.z = fmaf(ex2_approx(dtv * c2[2]), h.z, u * Bm.z);
        h.w = fmaf(ex2_approx(dtv * c2[3]), h.w, u * Bm.w);
        float part = h.x * Cm.x + h.y * Cm.y + h.z * Cm.z + h.w * Cm.w;
        part += __shfl_xor_sync(0xffffffffu, part, 1);
        part += __shfl_xor_sync(0xffffffffu, part, 2);
        if (nq == 0 && l >= (CS - PL)) {
            int li = l - (CS - PL);
            long zo = ((long)b * PL + li) * DIN + d;
            float zv = z96[zo];
            float yv = (part + xcv * Dd) * (zv * fast_sigmoid(zv));
            y96[zo] = yv;
        }
    }
}

// ---------------- compose W_fc @ W_out -> [COUT, DIN] ----------------
__global__ void wcomb_kernel(const float* __restrict__ Wfc,
                             const float* __restrict__ Wout,
                             float* __restrict__ Wc) {
    int idx = blockIdx.x * blockDim.x + threadIdx.x;
    if (idx >= COUT * DIN) return;
    int j = idx & (DIN - 1);
    int i = idx >> 9;
    float s = 0.f;
    #pragma unroll 4
    for (int k = 0; k < DM; ++k)
        s = fmaf(Wfc[i * DM + k], Wout[(long)k * DIN + j], s);
    Wc[idx] = s;
}

// ---------------- launcher ----------------
extern "C" void kernel_launch(void* const* d_in, const int* in_sizes, int n_in,
                              void* d_out, int out_size) {
    const float* x_enc  = (const float*)d_in[0];
    const float* x_mark = (const float*)d_in[1];
    const float* W_it   = (const float*)d_in[4];
    const float* b_it   = (const float*)d_in[5];
    const float* W_in   = (const float*)d_in[6];
    const float* conv_w = (const float*)d_in[7];
    const float* conv_b = (const float*)d_in[8];
    const float* W_x    = (const float*)d_in[9];
    const float* W_dt   = (const float*)d_in[10];
    const float* b_dt   = (const float*)d_in[11];
    const float* A_log  = (const float*)d_in[12];
    const float* Dv     = (const float*)d_in[13];
    const float* W_out  = (const float*)d_in[14];
    const float* W_fc   = (const float*)d_in[15];
    const float* b_fc   = (const float*)d_in[16];
    float* out = (float*)d_out;

    float *p_cat, *p_x, *p_xp, *p_z96, *p_xc, *p_db, *p_dt;
    float *p_P, *p_Q, *p_hin, *p_y96, *p_wc;
    cudaGetSymbolAddress((void**)&p_cat, g_cat);
    cudaGetSymbolAddress((void**)&p_x,   g_x);
    cudaGetSymbolAddress((void**)&p_xp,  g_xp);
    cudaGetSymbolAddress((void**)&p_z96, g_z96);
    cudaGetSymbolAddress((void**)&p_xc,  g_xc);
    cudaGetSymbolAddress((void**)&p_db,  g_db);
    cudaGetSymbolAddress((void**)&p_dt,  g_dt);
    cudaGetSymbolAddress((void**)&p_P,   g_P);
    cudaGetSymbolAddress((void**)&p_Q,   g_Q);
    cudaGetSymbolAddress((void**)&p_hin, g_hin);
    cudaGetSymbolAddress((void**)&p_y96, g_y96);
    cudaGetSymbolAddress((void**)&p_wc,  g_wc);

    // 1) concat inputs
    concat_kernel<<<(MROWS * CIN + 255) / 256, 256>>>(x_enc, x_mark, p_cat);
    // 2) input projection: x = cat @ W_it^T + b_it   [16384 x 256]
    sgemm_kernel<<<dim3(DM / 64, MROWS / 64), 128>>>(p_cat, W_it, b_it, p_x,
                                                     MROWS, DM, CIN, CIN, 0, 0);
    // 3) xp = x @ W_in[0:512]^T  (all rows)
    sgemm_kernel<<<dim3(DIN / 64, MROWS / 64), 128>>>(p_x, W_in, nullptr, p_xp,
                                                      MROWS, DIN, DM, DM, 0, 0);
    // 4) z = x @ W_in[512:1024]^T  (only last 96 timesteps per batch)
    sgemm_kernel<<<dim3(DIN / 64, (BATCH * PL) / 64), 128>>>(
        p_x, W_in + (long)DIN * DM, nullptr, p_z96, BATCH * PL, DIN, DM, DM, 0, 1);
    // 5) causal depthwise conv + silu
    conv_silu_kernel<<<(int)(((long)MROWS * DIN + 255) / 256), 256>>>(p_xp, conv_w,
                                                                      conv_b, p_xc);
    // 6) x_db = xc @ W_x^T   [16384 x 48]
    sgemm_kernel<<<dim3(1, MROWS / 64), 128>>>(p_xc, W_x, nullptr, p_db,
                                               MROWS, 48, DIN, DIN, 0, 0);
    // 7) dt = softplus(dt_raw @ W_dt^T + b_dt)   [16384 x 512]
    sgemm_kernel<<<dim3(DIN / 64, MROWS / 64), 128>>>(p_db, W_dt, b_dt, p_dt,
                                                      MROWS, DIN, DTR, 48, 1, 0);
    // 8) chunked selective scan
    scan_pass1<<<dim3(16, BATCH, NPRE), 128>>>(p_dt, p_xc, p_db, A_log, p_P, p_Q);
    scan_pass2<<<(BATCH * DIN * 4 + 255) / 256, 256>>>(p_P, p_Q, p_hin);
    scan_pass3<<<dim3(16, BATCH), 128>>>(p_dt, p_xc, p_db, A_log, p_hin, p_z96,
                                         Dv, p_y96);
    // 9) output: compose W_fc@W_out once, then single GEMM on 768 rows
    wcomb_kernel<<<(COUT * DIN + 255) / 256, 256>>>(W_fc, W_out, p_wc);
    sgemm_kernel<<<dim3(1, (BATCH * PL) / 64), 128>>>(p_y96, p_wc, b_fc, out,
                                                      BATCH * PL, COUT, DIN, DIN, 0, 0);
}

// round 4
// speedup vs baseline: 1.4964x; 1.4964x over previous
#include <cuda_runtime.h>
#include <math.h>

// ---------------- problem constants ----------------
#define BATCH 8
#define LSEQ  2048
#define EIN   64
#define MARK  4
#define CIN   68
#define CINP  80          // padded K for fused input GEMM (multiple of 16)
#define DM    256
#define DIN   512
#define DST   16
#define DTR   16
#define PL    96
#define COUT  64
#define MROWS (BATCH*LSEQ)   // 16384
#define CS    128
#define NCH   (LSEQ/CS)      // 16
#define NPRE  (NCH-1)        // 15
#define LOUT0 (LSEQ-PL)      // 1952

// ---------------- scratch (static device memory; no allocs) ----------------
__device__ __align__(16) float g_cat [MROWS*CINP];
__device__ __align__(16) float g_xp  [MROWS*DIN];
__device__ __align__(16) float g_z96 [BATCH*PL*DIN];
__device__ __align__(16) float g_xc  [MROWS*DIN];
__device__ __align__(16) float g_db  [MROWS*48];
__device__ __align__(16) float g_dt  [MROWS*DIN];
__device__ __align__(16) float g_P   [BATCH*NPRE*DIN*DST];
__device__ __align__(16) float g_Q   [BATCH*NPRE*DIN*DST];
__device__ __align__(16) float g_hin [BATCH*DIN*DST];
__device__ __align__(16) float g_y96 [BATCH*PL*DIN];
__device__ __align__(16) float g_w1  [DIN*CINP];   // W_in_xp @ W_it (padded)
__device__ __align__(16) float g_b1  [DIN];
__device__ __align__(16) float g_wz  [DIN*CINP];   // W_in_z @ W_it (padded)
__device__ __align__(16) float g_bz  [DIN];
__device__ __align__(16) float g_wc  [COUT*DIN];   // W_fc @ W_out

// ---------------- helpers ----------------
__device__ __forceinline__ float ex2_approx(float x) {
    float r;
    asm("ex2.approx.ftz.f32 %0, %1;" : "=f"(r) : "f"(x));
    return r;
}
__device__ __forceinline__ float fast_sigmoid(float x) {
    return 1.0f / (1.0f + __expf(-x));
}

// ---------------- K0: concat(x_enc, x_mark) with zero pad to CINP ----------
__global__ void concat_kernel(const float* __restrict__ xe,
                              const float* __restrict__ xm,
                              float* __restrict__ cat) {
    int idx = blockIdx.x * blockDim.x + threadIdx.x;
    if (idx >= MROWS * CINP) return;
    int c  = idx % CINP;
    int bl = idx / CINP;
    float v = 0.f;
    if (c < EIN)      v = xe[(long)bl * EIN + c];
    else if (c < CIN) v = xm[(long)bl * MARK + (c - EIN)];
    cat[idx] = v;
}

// ---------------- weight fusion: Wf[n][k] = sum_j Wpart[n][j]*W_it[j][k] ------
// idx over N*(CINP+1); k==CINP slot computes fused bias = Wpart@b_it.
__global__ void wfuse_kernel(const float* __restrict__ Wpart,  // [DIN, DM]
                             const float* __restrict__ Wit,    // [DM, CIN]
                             const float* __restrict__ bit,    // [DM]
                             float* __restrict__ Wf,           // [DIN, CINP]
                             float* __restrict__ bf) {         // [DIN]
    int idx = blockIdx.x * blockDim.x + threadIdx.x;
    if (idx >= DIN * (CINP + 1)) return;
    int k = idx % (CINP + 1);
    int n = idx / (CINP + 1);
    if (k == CINP) {
        float s = 0.f;
        #pragma unroll 4
        for (int j = 0; j < DM; ++j) s = fmaf(Wpart[(long)n * DM + j], bit[j], s);
        bf[n] = s;
        return;
    }
    float s = 0.f;
    if (k < CIN) {
        #pragma unroll 4
        for (int j = 0; j < DM; ++j)
            s = fmaf(Wpart[(long)n * DM + j], Wit[(long)j * CIN + k], s);
    }
    Wf[(long)n * CINP + k] = s;
}

// ---------------- compose W_fc @ W_out -> [COUT, DIN] ----------------
__global__ void wcomb_kernel(const float* __restrict__ Wfc,
                             const float* __restrict__ Wout,
                             float* __restrict__ Wc) {
    int idx = blockIdx.x * blockDim.x + threadIdx.x;
    if (idx >= COUT * DIN) return;
    int j = idx & (DIN - 1);
    int i = idx >> 9;
    float s = 0.f;
    #pragma unroll 4
    for (int k = 0; k < DM; ++k)
        s = fmaf(Wfc[i * DM + k], Wout[(long)k * DIN + j], s);
    Wc[idx] = s;
}

// ---------------- main SGEMM: C[M,N] = A[M,K(lda)] @ W[N,K]^T (+bias)(+act) --
// BM=128, BN=64, BK=16, 256 threads, 8x4 per thread. Requires:
//   M % 128 == 0, K % 16 == 0, lda % 4 == 0, N % 4 == 0, A/W/C 16B aligned.
__global__ __launch_bounds__(256)
void sgemm_kernel(const float* __restrict__ A, const float* __restrict__ W,
                  const float* __restrict__ bias, float* __restrict__ C,
                  int M, int N, int K, int lda, int act) {
    __shared__ float As[16][132];
    __shared__ float Bs[16][68];
    const int bm = blockIdx.y * 128;
    const int bn = blockIdx.x * 64;
    const int tid = threadIdx.x;
    const int tx = tid & 15;          // 16 n-groups (x4)
    const int ty = tid >> 4;          // 16 m-groups (x8)

    float acc[8][4];
    #pragma unroll
    for (int i = 0; i < 8; i++)
        #pragma unroll
        for (int j = 0; j < 4; j++) acc[i][j] = 0.f;

    // B-load indices: one float4 per thread
    const int bln = tid >> 2;         // 0..63
    const int blk = tid & 3;          // 0..3
    const int kt = K >> 4;
    for (int t = 0; t < kt; ++t) {
        const int k0 = t << 4;
        // load A tile: 2 float4 per thread
        #pragma unroll
        for (int i = 0; i < 2; ++i) {
            int vec = tid + i * 256;          // 0..511
            int row = vec >> 2;
            int kq  = vec & 3;
            float4 a4 = *(const float4*)(A + (long)(bm + row) * lda + k0 + kq * 4);
            As[kq * 4 + 0][row] = a4.x;
            As[kq * 4 + 1][row] = a4.y;
            As[kq * 4 + 2][row] = a4.z;
            As[kq * 4 + 3][row] = a4.w;
        }
        // load B tile: 1 float4 per thread (guard N)
        {
            int gn = bn + bln;
            float4 b4 = make_float4(0.f, 0.f, 0.f, 0.f);
            if (gn < N) b4 = *(const float4*)(W + (long)gn * K + k0 + blk * 4);
            Bs[blk * 4 + 0][bln] = b4.x;
            Bs[blk * 4 + 1][bln] = b4.y;
            Bs[blk * 4 + 2][bln] = b4.z;
            Bs[blk * 4 + 3][bln] = b4.w;
        }
        __syncthreads();
        #pragma unroll
        for (int kk = 0; kk < 16; ++kk) {
            float4 a0 = *(const float4*)&As[kk][ty * 8];
            float4 a1 = *(const float4*)&As[kk][ty * 8 + 4];
            float4 b  = *(const float4*)&Bs[kk][tx * 4];
            float am[8] = {a0.x, a0.y, a0.z, a0.w, a1.x, a1.y, a1.z, a1.w};
            float bn_[4] = {b.x, b.y, b.z, b.w};
            #pragma unroll
            for (int i = 0; i < 8; i++)
                #pragma unroll
                for (int j = 0; j < 4; j++)
                    acc[i][j] = fmaf(am[i], bn_[j], acc[i][j]);
        }
        __syncthreads();
    }
    const int gn0 = bn + tx * 4;
    if (gn0 >= N) return;
    float bv[4] = {0.f, 0.f, 0.f, 0.f};
    if (bias) {
        #pragma unroll
        for (int j = 0; j < 4; j++) bv[j] = bias[gn0 + j];
    }
    #pragma unroll
    for (int i = 0; i < 8; i++) {
        int gm = bm + ty * 8 + i;
        float4 o;
        float v0 = acc[i][0] + bv[0];
        float v1 = acc[i][1] + bv[1];
        float v2 = acc[i][2] + bv[2];
        float v3 = acc[i][3] + bv[3];
        if (act == 1) {   // softplus
            v0 = (v0 > 20.f) ? v0 : log1pf(__expf(v0));
            v1 = (v1 > 20.f) ? v1 : log1pf(__expf(v1));
            v2 = (v2 > 20.f) ? v2 : log1pf(__expf(v2));
            v3 = (v3 > 20.f) ? v3 : log1pf(__expf(v3));
        }
        o.x = v0; o.y = v1; o.z = v2; o.w = v3;
        *(float4*)(C + (long)gm * N + gn0) = o;
    }
}

// ---------------- small GEMM: one thread per output element -----------------
// C[M,N] = A[M,K(lda)] @ W[N,K]^T + bias. remap: A row = last-96 mapping.
__global__ void small_gemm(const float* __restrict__ A, const float* __restrict__ W,
                           const float* __restrict__ bias, float* __restrict__ C,
                           int M, int N, int K, int lda, int remap) {
    int idx = blockIdx.x * blockDim.x + threadIdx.x;
    if (idx >= M * N) return;
    int j = idx % N;
    int i = idx / N;
    int row = i;
    if (remap) row = (i / PL) * LSEQ + LOUT0 + (i % PL);
    const float* a = A + (long)row * lda;
    const float* w = W + (long)j * K;
    float s = 0.f;
    for (int k = 0; k < K; k += 4) {
        float4 av = *(const float4*)(a + k);
        float4 wv = *(const float4*)(w + k);
        s = fmaf(av.x, wv.x, s);
        s = fmaf(av.y, wv.y, s);
        s = fmaf(av.z, wv.z, s);
        s = fmaf(av.w, wv.w, s);
    }
    if (bias) s += bias[j];
    C[idx] = s;
}

// ---------------- causal depthwise conv(4) + bias + silu ----------------
__global__ void conv_silu_kernel(const float* __restrict__ xp,
                                 const float* __restrict__ cw,
                                 const float* __restrict__ cb,
                                 float* __restrict__ xc) {
    long idx = (long)blockIdx.x * blockDim.x + threadIdx.x;
    if (idx >= (long)MROWS * DIN) return;
    int d = (int)(idx & (DIN - 1));
    int l = (int)((idx >> 9) & (LSEQ - 1));
    float4 w = *(const float4*)(cw + d * 4);
    float acc = cb[d];
    if (l >= 3) acc = fmaf(xp[idx - 3 * DIN], w.x, acc);
    if (l >= 2) acc = fmaf(xp[idx - 2 * DIN], w.y, acc);
    if (l >= 1) acc = fmaf(xp[idx - 1 * DIN], w.z, acc);
    acc = fmaf(xp[idx], w.w, acc);
    xc[idx] = acc * fast_sigmoid(acc);
}

// ---------------- scan pass 1: prefix chunks -> (P, Q) ----------------
__global__ __launch_bounds__(128)
void scan_pass1(const float* __restrict__ dt, const float* __restrict__ xc,
                const float* __restrict__ db, const float* __restrict__ A_log,
                float* __restrict__ P, float* __restrict__ Q) {
    int tid = threadIdx.x;
    int nq = tid & 3;
    int dl = tid >> 2;
    int d  = blockIdx.x * 32 + dl;
    int b  = blockIdx.y;
    int c  = blockIdx.z;
    int l0 = c * CS;
    const float LOG2E = 1.4426950408889634f;
    float c2[4];
    #pragma unroll
    for (int i = 0; i < 4; i++)
        c2[i] = -__expf(A_log[d * DST + nq * 4 + i]) * LOG2E;
    float h0 = 0.f, h1 = 0.f, h2 = 0.f, h3 = 0.f, S = 0.f;
    const float* dtp = dt + ((long)b * LSEQ + l0) * DIN + d;
    const float* xcp = xc + ((long)b * LSEQ + l0) * DIN + d;
    const float* dbp = db + ((long)b * LSEQ + l0) * 48 + 16 + nq * 4;
    #pragma unroll 4
    for (int l = 0; l < CS; ++l) {
        float dtv = dtp[(long)l * DIN];
        float xcv = xcp[(long)l * DIN];
        float4 Bm = *(const float4*)(dbp + (long)l * 48);
        S += dtv;
        float u = dtv * xcv;
        h0 = fmaf(ex2_approx(dtv * c2[0]), h0, u * Bm.x);
        h1 = fmaf(ex2_approx(dtv * c2[1]), h1, u * Bm.y);
        h2 = fmaf(ex2_approx(dtv * c2[2]), h2, u * Bm.z);
        h3 = fmaf(ex2_approx(dtv * c2[3]), h3, u * Bm.w);
    }
    long o = ((long)(b * NPRE + c) * DIN + d) * DST + nq * 4;
    *(float4*)(P + o) = make_float4(ex2_approx(S * c2[0]), ex2_approx(S * c2[1]),
                                    ex2_approx(S * c2[2]), ex2_approx(S * c2[3]));
    *(float4*)(Q + o) = make_float4(h0, h1, h2, h3);
}

// ---------------- scan pass 2: compose chunks ----------------
__global__ void scan_pass2(const float* __restrict__ P, const float* __restrict__ Q,
                           float* __restrict__ Hin) {
    int idx = blockIdx.x * blockDim.x + threadIdx.x;
    if (idx >= BATCH * DIN * 4) return;
    int nq = idx & 3;
    int d  = (idx >> 2) & (DIN - 1);
    int b  = idx >> 11;
    float4 h = make_float4(0.f, 0.f, 0.f, 0.f);
    for (int c = 0; c < NPRE; ++c) {
        long o = ((long)(b * NPRE + c) * DIN + d) * DST + nq * 4;
        float4 p = *(const float4*)(P + o);
        float4 q = *(const float4*)(Q + o);
        h.x = fmaf(p.x, h.x, q.x);
        h.y = fmaf(p.y, h.y, q.y);
        h.z = fmaf(p.z, h.z, q.z);
        h.w = fmaf(p.w, h.w, q.w);
    }
    *(float4*)(Hin + (long)idx * 4) = h;
}

// ---------------- scan pass 3: replay last chunk, emit gated y ----------------
__global__ __launch_bounds__(128)
void scan_pass3(const float* __restrict__ dt, const float* __restrict__ xc,
                const float* __restrict__ db, const float* __restrict__ A_log,
                const float* __restrict__ Hin, const float* __restrict__ z96,
                const float* __restrict__ Dv, float* __restrict__ y96) {
    int tid = threadIdx.x;
    int nq = tid & 3;
    int dl = tid >> 2;
    int d  = blockIdx.x * 32 + dl;
    int b  = blockIdx.y;
    int l0 = (NCH - 1) * CS;
    const float LOG2E = 1.4426950408889634f;
    float c2[4];
    #pragma unroll
    for (int i = 0; i < 4; i++)
        c2[i] = -__expf(A_log[d * DST + nq * 4 + i]) * LOG2E;
    float4 h = *(const float4*)(Hin + (((long)b * DIN + d) * DST + nq * 4));
    float Dd = Dv[d];
    const float* dtp = dt + ((long)b * LSEQ + l0) * DIN + d;
    const float* xcp = xc + ((long)b * LSEQ + l0) * DIN + d;
    const float* dbp = db + ((long)b * LSEQ + l0) * 48 + 16 + nq * 4;
    #pragma unroll 2
    for (int l = 0; l < CS; ++l) {
        float dtv = dtp[(long)l * DIN];
        float xcv = xcp[(long)l * DIN];
        float4 Bm = *(const float4*)(dbp + (long)l * 48);
        float4 Cm = *(const float4*)(dbp + (long)l * 48 + 16);
        float u = dtv * xcv;
        h.x = fmaf(ex2_approx(dtv * c2[0]), h.x, u * Bm.x);
        h.y = fmaf(ex2_approx(dtv * c2[1]), h.y, u * Bm.y);
        h.z = fmaf(ex2_approx(dtv * c2[2]), h.z, u * Bm.z);
        h.w = fmaf(ex2_approx(dtv * c2[3]), h.w, u * Bm.w);
        float part = h.x * Cm.x + h.y * Cm.y + h.z * Cm.z + h.w * Cm.w;
        part += __shfl_xor_sync(0xffffffffu, part, 1);
        part += __shfl_xor_sync(0xffffffffu, part, 2);
        if (nq == 0 && l >= (CS - PL)) {
            int li = l - (CS - PL);
            long zo = ((long)b * PL + li) * DIN + d;
            float zv = z96[zo];
            float yv = (part + xcv * Dd) * (zv * fast_sigmoid(zv));
            y96[zo] = yv;
        }
    }
}

// ---------------- launcher ----------------
extern "C" void kernel_launch(void* const* d_in, const int* in_sizes, int n_in,
                              void* d_out, int out_size) {
    const float* x_enc  = (const float*)d_in[0];
    const float* x_mark = (const float*)d_in[1];
    const float* W_it   = (const float*)d_in[4];
    const float* b_it   = (const float*)d_in[5];
    const float* W_in   = (const float*)d_in[6];
    const float* conv_w = (const float*)d_in[7];
    const float* conv_b = (const float*)d_in[8];
    const float* W_x    = (const float*)d_in[9];
    const float* W_dt   = (const float*)d_in[10];
    const float* b_dt   = (const float*)d_in[11];
    const float* A_log  = (const float*)d_in[12];
    const float* Dv     = (const float*)d_in[13];
    const float* W_out  = (const float*)d_in[14];
    const float* W_fc   = (const float*)d_in[15];
    const float* b_fc   = (const float*)d_in[16];
    float* out = (float*)d_out;

    float *p_cat, *p_xp, *p_z96, *p_xc, *p_db, *p_dt;
    float *p_P, *p_Q, *p_hin, *p_y96, *p_w1, *p_b1, *p_wz, *p_bz, *p_wc;
    cudaGetSymbolAddress((void**)&p_cat, g_cat);
    cudaGetSymbolAddress((void**)&p_xp,  g_xp);
    cudaGetSymbolAddress((void**)&p_z96, g_z96);
    cudaGetSymbolAddress((void**)&p_xc,  g_xc);
    cudaGetSymbolAddress((void**)&p_db,  g_db);
    cudaGetSymbolAddress((void**)&p_dt,  g_dt);
    cudaGetSymbolAddress((void**)&p_P,   g_P);
    cudaGetSymbolAddress((void**)&p_Q,   g_Q);
    cudaGetSymbolAddress((void**)&p_hin, g_hin);
    cudaGetSymbolAddress((void**)&p_y96, g_y96);
    cudaGetSymbolAddress((void**)&p_w1,  g_w1);
    cudaGetSymbolAddress((void**)&p_b1,  g_b1);
    cudaGetSymbolAddress((void**)&p_wz,  g_wz);
    cudaGetSymbolAddress((void**)&p_bz,  g_bz);
    cudaGetSymbolAddress((void**)&p_wc,  g_wc);

    // 0) weight fusion (small, overlaps with concat on the same stream order)
    concat_kernel<<<(MROWS * CINP + 255) / 256, 256>>>(x_enc, x_mark, p_cat);
    wfuse_kernel<<<(DIN * (CINP + 1) + 255) / 256, 256>>>(W_in, W_it, b_it, p_w1, p_b1);
    wfuse_kernel<<<(DIN * (CINP + 1) + 255) / 256, 256>>>(W_in + (long)DIN * DM,
                                                          W_it, b_it, p_wz, p_bz);
    wcomb_kernel<<<(COUT * DIN + 255) / 256, 256>>>(W_fc, W_out, p_wc);

    // 1) fused input+in_proj GEMM: xp = cat @ W1^T + b1   [16384 x 512], K=80
    sgemm_kernel<<<dim3(DIN / 64, MROWS / 128), 256>>>(p_cat, p_w1, p_b1, p_xp,
                                                       MROWS, DIN, CINP, CINP, 0);
    // 2) z (last 96 rows only): z = cat96 @ Wz^T + bz
    small_gemm<<<(BATCH * PL * DIN + 255) / 256, 256>>>(p_cat, p_wz, p_bz, p_z96,
                                                        BATCH * PL, DIN, CINP, CINP, 1);
    // 3) causal depthwise conv + silu
    conv_silu_kernel<<<(int)(((long)MROWS * DIN + 255) / 256), 256>>>(p_xp, conv_w,
                                                                      conv_b, p_xc);
    // 4) x_db = xc @ W_x^T   [16384 x 48]
    sgemm_kernel<<<dim3(1, MROWS / 128), 256>>>(p_xc, W_x, nullptr, p_db,
                                                MROWS, 48, DIN, DIN, 0);
    // 5) dt = softplus(db[:, :16] @ W_dt^T + b_dt)   [16384 x 512]
    sgemm_kernel<<<dim3(DIN / 64, MROWS / 128), 256>>>(p_db, W_dt, b_dt, p_dt,
                                                       MROWS, DIN, DTR, 48, 1);
    // 6) chunked selective scan
    scan_pass1<<<dim3(16, BATCH, NPRE), 128>>>(p_dt, p_xc, p_db, A_log, p_P, p_Q);
    scan_pass2<<<(BATCH * DIN * 4 + 255) / 256, 256>>>(p_P, p_Q, p_hin);
    scan_pass3<<<dim3(16, BATCH), 128>>>(p_dt, p_xc, p_db, A_log, p_hin, p_z96,
                                         Dv, p_y96);
    // 7) output: out = y96 @ (W_fc@W_out)^T + b_fc
    small_gemm<<<(BATCH * PL * COUT + 255) / 256, 256>>>(p_y96, p_wc, b_fc, out,
                                                         BATCH * PL, COUT, DIN, DIN, 0);
}